// round 16
// baseline (speedup 1.0000x reference)
#include <cuda_runtime.h>
#include <cuda_fp16.h>

// Problem constants (fixed by reference setup)
#define BSZ     2
#define SEQ     4096
#define HQN     32
#define HKV     2
#define DIM     128
#define NBL     255
#define GRP     16
#define SCALE   0.08838834764831845f   // 1/sqrt(128)

#define OUT_ELEMS  ((size_t)BSZ*SEQ*HQN*DIM)            // 33,554,432
#define ATTN_ELEMS ((size_t)BSZ*HQN*SEQ*NBL)            // 66,846,720

typedef unsigned long long ull;
typedef unsigned int       u32;

// Compressed K/V in fp16. nb padded to 256; index 255 stays zero
// (device globals are zero-initialized; row 255 is never written).
// K: [bh][nb(256)][d(128)]   V (pre-transposed): [bh][d(128)][nb(256)]
__device__ __half g_k16 [4*256*128];
__device__ __half g_vt16[4*128*256];
// W pre-converted to fp16: [t][e(4096)][d(128)]
__device__ __half g_w16 [2*4096*128];

// ---- warp-MMA helpers (sm_80-class, valid on non-'a' target) --------------
__device__ __forceinline__ u32 smem_u32(const void* p) {
    u32 a; asm("{ .reg .u64 t; cvta.to.shared.u64 t, %1; cvt.u32.u64 %0, t; }"
               : "=r"(a) : "l"(p));
    return a;
}
__device__ __forceinline__ void ldsm4(u32* r, u32 addr) {
    asm volatile("ldmatrix.sync.aligned.m8n8.x4.shared.b16 {%0,%1,%2,%3}, [%4];"
        : "=r"(r[0]), "=r"(r[1]), "=r"(r[2]), "=r"(r[3]) : "r"(addr));
}
__device__ __forceinline__ void ldsm4t(u32* r, u32 addr) {
    asm volatile("ldmatrix.sync.aligned.m8n8.x4.trans.shared.b16 {%0,%1,%2,%3}, [%4];"
        : "=r"(r[0]), "=r"(r[1]), "=r"(r[2]), "=r"(r[3]) : "r"(addr));
}
__device__ __forceinline__ void mma16816(float* d, const u32* a, u32 b0, u32 b1) {
    asm volatile("mma.sync.aligned.m16n8k16.row.col.f32.f16.f16.f32 "
        "{%0,%1,%2,%3},{%4,%5,%6,%7},{%8,%9},{%0,%1,%2,%3};"
        : "+f"(d[0]), "+f"(d[1]), "+f"(d[2]), "+f"(d[3])
        : "r"(a[0]), "r"(a[1]), "r"(a[2]), "r"(a[3]), "r"(b0), "r"(b1));
}
__device__ __forceinline__ u32 pkhf(__half a, __half b) {
    __half2 t(a, b);                        // .x at low halfword
    return *(u32*)&t;
}
#define CP_A16(dst, src) \
    asm volatile("cp.async.cg.shared.global [%0], [%1], 16;" \
                 :: "r"(dst), "l"(src) : "memory")
#define CP_COMMIT()  asm volatile("cp.async.commit_group;" ::: "memory")
#define CP_WAIT(N)   asm volatile("cp.async.wait_group %0;" :: "n"(N) : "memory")

// ---------------------------------------------------------------------------
// W fp32 -> fp16 conversion. grid (512, 2), block 256. 131072 float4 per t.
// ---------------------------------------------------------------------------
__global__ __launch_bounds__(256)
void wconv_kernel(const float* __restrict__ wk, const float* __restrict__ wv)
{
    const float* src = blockIdx.y ? wv : wk;
    __half* dst = g_w16 + (size_t)blockIdx.y * 524288;
    int i = blockIdx.x * 256 + threadIdx.x;
    float4 v = ((const float4*)src)[i];
    uint2 o;
    o.x = pkhf(__float2half_rn(v.x), __float2half_rn(v.y));
    o.y = pkhf(__float2half_rn(v.z), __float2half_rn(v.w));
    ((uint2*)dst)[i] = o;
}

// ---------------------------------------------------------------------------
// Compression via HMMA. grid (16 nbg, 4 bh, 2 t), block 256 (8 warps).
// Per CTA: C[16 nb, 128 d] = A[16, 4096]·W[4096, 128], K streamed as 32
// blk-chunks of 128 e-values. A[nb, blk*128+dd] = x[(nb0+nb)*16+blk][dd] +
// pe[blk][dd], staged fp32-add + fp16-convert into a 4KB swizzled buffer.
// W chunks (32KB fp16, k-major [e][d]) stream via cp.async double-buffer
// from g_w16; B fragments via ldmatrix.x4.trans. Warp w owns d-cols w*16.
// cp.async LEDGER: prologue commits w0, w1; every loop iter commits exactly
// ONE group (empty when blk+2 >= 32) after the compute-done sync, then
// CP_WAIT(1) drains w_{blk+1}. Buffer reuse is barrier-protected.
// SMEM: A 2x4KB @0 | W 2x32KB @8192   total 73,728 B   (2 CTAs/SM)
// ---------------------------------------------------------------------------
#define CM_A_OFF 0
#define CM_W_OFF 8192
#define CM_SMEM  73728

__global__ __launch_bounds__(256, 2)
void compress_mma(const float* __restrict__ kin, const float* __restrict__ vin,
                  const float* __restrict__ pek, const float* __restrict__ pev)
{
    extern __shared__ char smc[];
    const u32 sb = smem_u32(smc);

    const int nbg = blockIdx.x;              // 0..15
    const int bh  = blockIdx.y;              // b*2+h
    const int b   = bh >> 1, h = bh & 1;
    const int t   = blockIdx.z;              // 0=k, 1=v

    const float*  x    = t ? vin : kin;
    const float*  pe   = t ? pev : pek;
    const __half* w16g = g_w16 + (size_t)t * 524288;

    const int tid  = threadIdx.x;
    const int w    = tid >> 5;
    const int lane = tid & 31;
    const int li = lane & 15, lh = lane >> 4;
    const int gq = lane >> 2, tq = lane & 3;
    const int dw = w * 16;                   // warp's d-range [dw, dw+16)
    const int nb0 = nbg * 16;

    // -- A stage: chunk blk -> Abuf[buf] (16 rows x 128 e fp16, swizzled) --
    auto a_stage = [&](int blk, int buf) {
        const int row = tid >> 4;            // 0..15
        const int c2  = tid & 15;
        const int nb  = nb0 + row;
        const float* xrowp = x + ((size_t)(b * SEQ + nb * 16 + blk) * HKV + h) * DIM;
        const float* pep   = pe + blk * 128;
        char* abase = smc + CM_A_OFF + buf * 4096;
#pragma unroll
        for (int j = 0; j < 4; ++j) {
            int e2 = c2 + 16 * j;            // u32 index; dd = e2*2
            float2 xv = make_float2(0.f, 0.f);
            if (nb < NBL) xv = *(const float2*)(xrowp + e2 * 2);
            float2 pv = *(const float2*)(pep + e2 * 2);
            u32 off = (u32)row * 256 + ((((u32)e2 >> 2) ^ (row & 7)) << 4) + (e2 & 3) * 4;
            *(u32*)(abase + off) = pkhf(__float2half_rn(xv.x + pv.x),
                                        __float2half_rn(xv.y + pv.y));
        }
    };
    // -- W stage: chunk blk -> Wbuf[buf] via cp.async (128 e x 128 d fp16) --
    auto w_stage = [&](int blk, int buf) {
        const __half* wp = w16g + (size_t)blk * 16384;
        for (int u = tid; u < 2048; u += 256) {
            int e = u >> 4, cc = u & 15;
            u32 dst = sb + CM_W_OFF + buf * 32768
                    + (u32)e * 256 + (u32)((cc ^ (e & 7)) << 4);
            CP_A16(dst, wp + e * 128 + cc * 8);
        }
    };

    float acc[8];
#pragma unroll
    for (int i = 0; i < 8; ++i) acc[i] = 0.f;

    // prologue: w0, w1 committed; A0 staged; drain w0
    w_stage(0, 0); CP_COMMIT();
    w_stage(1, 1); CP_COMMIT();
    a_stage(0, 0);
    CP_WAIT(1);
    __syncthreads();

    for (int blk = 0; blk < 32; ++blk) {
        const int buf = blk & 1;
        // compute chunk blk: 8 k16 steps
#pragma unroll
        for (int ks = 0; ks < 8; ++ks) {
            u32 a4[4];
            ldsm4(a4, sb + CM_A_OFF + buf * 4096
                      + (u32)li * 256 + ((((u32)(ks * 2 + lh)) ^ (li & 7)) << 4));
            u32 b4[4];
            int e = ks * 16 + ((lane >> 3) & 1) * 8 + (lane & 7);
            u32 cd = (u32)((dw >> 3) + (lane >> 4));
            ldsm4t(b4, sb + CM_W_OFF + buf * 32768
                       + (u32)e * 256 + ((cd ^ (e & 7)) << 4));
            mma16816(acc,     a4, b4[0], b4[1]);   // n-tile dw..dw+8
            mma16816(acc + 4, a4, b4[2], b4[3]);   // n-tile dw+8..dw+16
        }
        __syncthreads();                      // all reads of buf done
        if (blk + 2 < 32) w_stage(blk + 2, buf);
        CP_COMMIT();                          // ALWAYS one group per iter
        if (blk + 1 < 32) a_stage(blk + 1, (blk + 1) & 1);
        CP_WAIT(1);                           // drains w_{blk+1}
        __syncthreads();
    }

    // -- Epilogue: C frags -> global fp16 outputs --
    const int nbr0 = nb0 + gq, nbr1 = nb0 + gq + 8;
    if (t == 0) {
        __half* base = g_k16 + (size_t)(bh * 256) * 128;
        if (nbr0 < NBL) {
            __half* p = base + (size_t)nbr0 * 128 + dw + 2 * tq;
            *(u32*)p       = pkhf(__float2half_rn(acc[0]), __float2half_rn(acc[1]));
            *(u32*)(p + 8) = pkhf(__float2half_rn(acc[4]), __float2half_rn(acc[5]));
        }
        if (nbr1 < NBL) {
            __half* p = base + (size_t)nbr1 * 128 + dw + 2 * tq;
            *(u32*)p       = pkhf(__float2half_rn(acc[2]), __float2half_rn(acc[3]));
            *(u32*)(p + 8) = pkhf(__float2half_rn(acc[6]), __float2half_rn(acc[7]));
        }
    } else {
        __half* vb = g_vt16 + (size_t)(bh * 128) * 256;
        const int d0 = dw + 2 * tq;
        if (nbr0 < NBL) {
            vb[(size_t)d0 * 256 + nbr0]       = __float2half_rn(acc[0]);
            vb[(size_t)(d0 + 1) * 256 + nbr0] = __float2half_rn(acc[1]);
            vb[(size_t)(d0 + 8) * 256 + nbr0] = __float2half_rn(acc[4]);
            vb[(size_t)(d0 + 9) * 256 + nbr0] = __float2half_rn(acc[5]);
        }
        if (nbr1 < NBL) {
            vb[(size_t)d0 * 256 + nbr1]       = __float2half_rn(acc[2]);
            vb[(size_t)(d0 + 1) * 256 + nbr1] = __float2half_rn(acc[3]);
            vb[(size_t)(d0 + 8) * 256 + nbr1] = __float2half_rn(acc[6]);
            vb[(size_t)(d0 + 9) * 256 + nbr1] = __float2half_rn(acc[7]);
        }
    }
}

// ---------------------------------------------------------------------------
// Attention kernel — fp16 warp MMA, 3 CTAs/SM. VERBATIM from R12 (passing).
// ---------------------------------------------------------------------------
#define SM_RMAX  0
#define SM_RSUM  1024
#define SM_Q     2048
#define SM_K     18432
#define SM_P     SM_K
#define SM_V0    51200
#define SM_V1    61440
#define ATT_SMEM 71680

__global__ __launch_bounds__(256, 3)
void attn_kernel(const float* __restrict__ q, float* __restrict__ out,
                 float* __restrict__ attn, int write_attn)
{
    extern __shared__ char smc[];
    const u32 sb = smem_u32(smc);
    float* rmax = (float*)(smc + SM_RMAX);   // [4 c4][64 rows]
    float* rsum = (float*)(smc + SM_RSUM);

    const int st = 63 - blockIdx.x;          // heavy-first
    const int g  = blockIdx.y;
    const int bh = blockIdx.z;
    const int b  = bh >> 1, h = bh & 1;
    const int hq = h * GRP + g;
    const int s0 = st * 64;
    const int tid  = threadIdx.x;
    const int w    = tid >> 5;
    const int lane = tid & 31;
    const int r2 = w >> 2, c4 = w & 3;
    const int gq = lane >> 2, tq = lane & 3;
    const int li = lane & 15, lh = lane >> 4;

    const int NVC = st * 4 + 3;              // max valid col count (odd)
    const int KR  = (NVC + 15) & ~15;        // total valid K rows (<=256)
    const int KR0 = min(KR, 128);
    const int KR1 = KR - KR0;                // >0 iff st>=32
    const int rbase = r2 * 32;
    const size_t bhoff = (size_t)bh * 32768;

    const int KSC = KR >> 4;                 // k16 steps for phase C (<=16)
    const int nch = (KSC + 1) >> 1;          // 32-nb V chunks (<=8)

    // ---- group 1: K half0 ----
    for (int u = tid; u < KR0 * 16; u += 256) {
        int nb = u >> 4, c = u & 15;
        u32 dst = sb + SM_K + (u32)nb * 256 + (u32)((c ^ (nb & 7)) << 4);
        CP_A16(dst, g_k16 + bhoff + nb * 128 + c * 8);
    }
    CP_COMMIT();
    // ---- group 2: V chunk 0 ----
    for (int u = tid; u < 512; u += 256) {
        int dd = u >> 2, cc = u & 3;
        CP_A16(sb + SM_V0 + (u32)dd * 80 + (u32)cc * 16,
               g_vt16 + bhoff + dd * 256 + cc * 8);
    }
    CP_COMMIT();
    // ---- group 3: V chunk 1 (EMPTY group when nch==1 — keeps the count) ----
    if (nch > 1) {
        for (int u = tid; u < 512; u += 256) {
            int dd = u >> 2, cc = u & 3;
            CP_A16(sb + SM_V1 + (u32)dd * 80 + (u32)cc * 16,
                   g_vt16 + bhoff + dd * 256 + 32 + cc * 8);
        }
    }
    CP_COMMIT();                              // ALWAYS the 3rd group
    // ---- Stage Q (f32 -> fp16), swizzled 256B rows ----
    for (int u = tid; u < 4096; u += 256) {
        int r = u >> 6, k2 = u & 63;
        float2 qv = *(const float2*)(q + ((size_t)((b * SEQ + s0 + r) * HQN + hq)) * DIM + k2 * 2);
        u32 off = (u32)r * 256 + (((((u32)k2) >> 2) ^ (r & 7)) << 4) + (k2 & 3) * 4;
        *(u32*)(smc + SM_Q + off) = pkhf(__float2half_rn(qv.x), __float2half_rn(qv.y));
    }
    CP_WAIT(2);                               // drains K half0 (3 groups committed)
    __syncthreads();

    // ---- Phase A: D[2 half][8 tile][4]; warp covers 32 cols per half ----
    float D[16][4];
#pragma unroll
    for (int i = 0; i < 16; ++i) { D[i][0] = D[i][1] = D[i][2] = D[i][3] = 0.f; }

#pragma unroll
    for (int hk = 0; hk < 2; ++hk) {
        if (hk == 1) {
            if (KR1 <= 0) break;
            __syncthreads();                  // all reads of K half0 done
            for (int u = tid; u < KR1 * 16; u += 256) {
                int nb = u >> 4, c = u & 15;
                u32 dst = sb + SM_K + (u32)nb * 256 + (u32)((c ^ (nb & 7)) << 4);
                CP_A16(dst, g_k16 + bhoff + (128 + nb) * 128 + c * 8);
            }
            CP_COMMIT();
            CP_WAIT(0);                       // drains V0/V1 too (issued early)
            __syncthreads();
        }
        const int cw = hk * 128 + c4 * 32;    // warp's first score col
        int jt = (NVC - cw + 7) >> 3;
        jt = (jt < 0) ? 0 : ((jt > 4) ? 4 : jt);
        const int ph = (jt + 1) >> 1;         // 16-col pairs (<=2)
        for (int ks = 0; ks < 8; ++ks) {
            u32 a2[2][4];
            const u32 ci = (u32)(ks * 2 + lh);
#pragma unroll
            for (int sp = 0; sp < 2; ++sp) {
                int ri = rbase + sp * 16 + li;
                ldsm4(a2[sp], sb + SM_Q + (u32)ri * 256 + ((ci ^ (ri & 7)) << 4));
            }
            for (int jp = 0; jp < ph; ++jp) {
                int ri = c4 * 32 + jp * 16 + li;      // local K row
                u32 b4[4];
                ldsm4(b4, sb + SM_K + (u32)ri * 256 + ((ci ^ (ri & 7)) << 4));
#pragma unroll
                for (int sp = 0; sp < 2; ++sp) {
                    mma16816(D[hk * 8 + sp * 4 + 2 * jp],     a2[sp], b4[0], b4[2]);
                    mma16816(D[hk * 8 + sp * 4 + 2 * jp + 1], a2[sp], b4[1], b4[3]);
                }
            }
        }
    }

    // ---- Softmax: local max -> B1 ----
#pragma unroll
    for (int slot = 0; slot < 4; ++slot) {
        int sp = slot >> 1, hf = slot & 1;
        int row = rbase + sp * 16 + gq + hf * 8;
        int s = s0 + row;
        int nv = (s >= 31) ? (((s - 31) >> 4) + 1) : 0;
        float mloc = -1e30f;
#pragma unroll
        for (int hk = 0; hk < 2; ++hk)
#pragma unroll
            for (int j = 0; j < 4; ++j) {
                int c0 = hk * 128 + c4 * 32 + j * 8 + 2 * tq;
                float* dd = D[hk * 8 + sp * 4 + j];
                if (c0     < nv) mloc = fmaxf(mloc, dd[hf * 2]     * SCALE);
                if (c0 + 1 < nv) mloc = fmaxf(mloc, dd[hf * 2 + 1] * SCALE);
            }
        mloc = fmaxf(mloc, __shfl_xor_sync(0xffffffffu, mloc, 1));
        mloc = fmaxf(mloc, __shfl_xor_sync(0xffffffffu, mloc, 2));
        if (tq == 0) rmax[c4 * 64 + row] = mloc;
    }
    __syncthreads();                          // B1

    // ---- Softmax: exp + sum -> B2 ----
#pragma unroll
    for (int slot = 0; slot < 4; ++slot) {
        int sp = slot >> 1, hf = slot & 1;
        int row = rbase + sp * 16 + gq + hf * 8;
        int s = s0 + row;
        int nv = (s >= 31) ? (((s - 31) >> 4) + 1) : 0;
        float m = fmaxf(fmaxf(rmax[row], rmax[64 + row]),
                        fmaxf(rmax[128 + row], rmax[192 + row]));
        float sl = 0.f;
#pragma unroll
        for (int hk = 0; hk < 2; ++hk)
#pragma unroll
            for (int j = 0; j < 4; ++j) {
                int c0 = hk * 128 + c4 * 32 + j * 8 + 2 * tq;
                float* dd = D[hk * 8 + sp * 4 + j];
                float e0 = (c0     < nv) ? __expf(dd[hf * 2]     * SCALE - m) : 0.f;
                float e1 = (c0 + 1 < nv) ? __expf(dd[hf * 2 + 1] * SCALE - m) : 0.f;
                dd[hf * 2]     = e0;
                dd[hf * 2 + 1] = e1;
                sl += e0 + e1;
            }
        sl += __shfl_xor_sync(0xffffffffu, sl, 1);
        sl += __shfl_xor_sync(0xffffffffu, sl, 2);
        if (tq == 0) rsum[c4 * 64 + row] = sl;
    }
    __syncthreads();                          // B2: K reads done -> P may overlay

    // ---- Normalize + attn write (scalar: NBL odd!) + P -> smem fp16 ----
#pragma unroll
    for (int slot = 0; slot < 4; ++slot) {
        int sp = slot >> 1, hf = slot & 1;
        int row = rbase + sp * 16 + gq + hf * 8;
        float tot = rsum[row] + rsum[64 + row] + rsum[128 + row] + rsum[192 + row];
        float inv = 1.f / fmaxf(tot, 1e-20f);
        size_t arow = (((size_t)b * HQN + hq) * SEQ + s0 + row) * NBL;
#pragma unroll
        for (int hk = 0; hk < 2; ++hk)
#pragma unroll
            for (int j = 0; j < 4; ++j) {
                int c0 = hk * 128 + c4 * 32 + j * 8 + 2 * tq;
                float* dd = D[hk * 8 + sp * 4 + j];
                float p0 = dd[hf * 2]     * inv;
                float p1 = dd[hf * 2 + 1] * inv;
                if (write_attn) {
                    attn[arow + c0] = p0;             // c0 <= 254 always
                    if (c0 + 1 < NBL) attn[arow + c0 + 1] = p1;
                }
                u32 ch = (u32)((hk * 16 + c4 * 4 + j) ^ (row & 7));
                u32 off = (u32)row * 512 + (ch << 4) + tq * 4;
                *(u32*)(smc + SM_P + off) = pkhf(__float2half_rn(p0), __float2half_rn(p1));
            }
    }
    __syncthreads();                          // B3: P visible

    // ---- Phase C: 32-nb V chunks, double-buffered ----
    const int dbase = c4 * 32;
    float C[8][4];
#pragma unroll
    for (int i = 0; i < 8; ++i) { C[i][0] = C[i][1] = C[i][2] = C[i][3] = 0.f; }

    for (int kc = 0; kc < nch; ++kc) {
        if (kc + 1 < nch) { CP_WAIT(1); }     // pending ⊆ {V_kc, V_kc+1} -> drains V_kc
        else             { CP_WAIT(0); }      // LAST chunk: nothing younger -> full drain
        __syncthreads();
        const u32 sbV = sb + ((kc & 1) ? SM_V1 : SM_V0);
        const int kslo = kc * 2;
        const int kshi = min(kslo + 2, KSC);
        for (int ks = kslo; ks < kshi; ++ks) {
            u32 p2[2][4];
            const u32 ciP = (u32)(ks * 2 + lh);
#pragma unroll
            for (int sp = 0; sp < 2; ++sp) {
                int ri = rbase + sp * 16 + li;
                ldsm4(p2[sp], sb + SM_P + (u32)ri * 512 + ((ciP ^ (ri & 7)) << 4));
            }
            const u32 ciV = (u32)((ks - kslo) * 2 + lh);
#pragma unroll
            for (int dp = 0; dp < 2; ++dp) {
                int ri = dbase + dp * 16 + li;
                u32 b4[4];
                ldsm4(b4, sbV + (u32)ri * 80 + ciV * 16);
#pragma unroll
                for (int sp = 0; sp < 2; ++sp) {
                    mma16816(C[sp * 4 + 2 * dp],     p2[sp], b4[0], b4[2]);
                    mma16816(C[sp * 4 + 2 * dp + 1], p2[sp], b4[1], b4[3]);
                }
            }
        }
        __syncthreads();                      // reads of chunk kc done
        if (kc + 2 < nch) {
            const u32 dstb = sb + ((kc & 1) ? SM_V1 : SM_V0);
            for (int u = tid; u < 512; u += 256) {
                int dd = u >> 2, cc = u & 3;
                CP_A16(dstb + (u32)dd * 80 + (u32)cc * 16,
                       g_vt16 + bhoff + dd * 256 + (kc + 2) * 32 + cc * 8);
            }
            CP_COMMIT();
        }
    }

    // ---- Store out: (BS, S, HQ, D), float2 per fragment pair ----
#pragma unroll
    for (int slot = 0; slot < 4; ++slot) {
        int sp = slot >> 1, hf = slot & 1;
        int row = rbase + sp * 16 + gq + hf * 8;
        float* op = out + ((size_t)(b * SEQ + s0 + row) * HQN + hq) * DIM + dbase;
#pragma unroll
        for (int dt = 0; dt < 4; ++dt) {
            *(float2*)(op + dt * 8 + 2 * tq) =
                make_float2(C[sp * 4 + dt][hf * 2], C[sp * 4 + dt][hf * 2 + 1]);
        }
    }
}

// ---------------------------------------------------------------------------
extern "C" void kernel_launch(void* const* d_in, const int* in_sizes, int n_in,
                              void* d_out, int out_size)
{
    const float* q   = (const float*)d_in[0];
    const float* k   = (const float*)d_in[1];
    const float* v   = (const float*)d_in[2];
    // d_in[3] = cu_seqlens_k (fixed [0,S,2S]) — unused
    const float* wk  = (const float*)d_in[4];
    const float* wv  = (const float*)d_in[5];
    const float* pek = (const float*)d_in[6];
    const float* pev = (const float*)d_in[7];

    float* out  = (float*)d_out;
    float* attn = out + OUT_ELEMS;
    int write_attn = ((size_t)out_size >= OUT_ELEMS + ATTN_ELEMS) ? 1 : 0;

    cudaFuncSetAttribute(compress_mma,
                         cudaFuncAttributeMaxDynamicSharedMemorySize, CM_SMEM);
    cudaFuncSetAttribute(attn_kernel,
                         cudaFuncAttributeMaxDynamicSharedMemorySize, ATT_SMEM);

    wconv_kernel<<<dim3(512, 2), 256>>>(wk, wv);
    compress_mma<<<dim3(16, 4, 2), 256, CM_SMEM>>>(k, v, pek, pev);
    attn_kernel<<<dim3(64, 16, 4), 256, ATT_SMEM>>>(q, out, attn, write_attn);
}

// round 17
// speedup vs baseline: 1.0107x; 1.0107x over previous
#include <cuda_runtime.h>
#include <cuda_fp16.h>

// Problem constants (fixed by reference setup)
#define BSZ     2
#define SEQ     4096
#define HQN     32
#define HKV     2
#define DIM     128
#define NBL     255
#define GRP     16
#define SCALE   0.08838834764831845f   // 1/sqrt(128)

#define OUT_ELEMS  ((size_t)BSZ*SEQ*HQN*DIM)            // 33,554,432
#define ATTN_ELEMS ((size_t)BSZ*HQN*SEQ*NBL)            // 66,846,720

typedef unsigned long long ull;
typedef unsigned int       u32;

// Compressed K/V in fp16. nb padded to 256; index 255 stays zero
// (device globals are zero-initialized; row 255 is never written).
// K: [bh][nb(256)][d(128)]   V (pre-transposed): [bh][d(128)][nb(256)]
__device__ __half g_k16 [4*256*128];
__device__ __half g_vt16[4*128*256];
// W pre-converted to fp16: [t][e(4096)][d(128)]
__device__ __half g_w16 [2*4096*128];

// ---- warp-MMA helpers (sm_80-class, valid on non-'a' target) --------------
__device__ __forceinline__ u32 smem_u32(const void* p) {
    u32 a; asm("{ .reg .u64 t; cvta.to.shared.u64 t, %1; cvt.u32.u64 %0, t; }"
               : "=r"(a) : "l"(p));
    return a;
}
__device__ __forceinline__ void ldsm4(u32* r, u32 addr) {
    asm volatile("ldmatrix.sync.aligned.m8n8.x4.shared.b16 {%0,%1,%2,%3}, [%4];"
        : "=r"(r[0]), "=r"(r[1]), "=r"(r[2]), "=r"(r[3]) : "r"(addr));
}
__device__ __forceinline__ void ldsm4t(u32* r, u32 addr) {
    asm volatile("ldmatrix.sync.aligned.m8n8.x4.trans.shared.b16 {%0,%1,%2,%3}, [%4];"
        : "=r"(r[0]), "=r"(r[1]), "=r"(r[2]), "=r"(r[3]) : "r"(addr));
}
__device__ __forceinline__ void mma16816(float* d, const u32* a, u32 b0, u32 b1) {
    asm volatile("mma.sync.aligned.m16n8k16.row.col.f32.f16.f16.f32 "
        "{%0,%1,%2,%3},{%4,%5,%6,%7},{%8,%9},{%0,%1,%2,%3};"
        : "+f"(d[0]), "+f"(d[1]), "+f"(d[2]), "+f"(d[3])
        : "r"(a[0]), "r"(a[1]), "r"(a[2]), "r"(a[3]), "r"(b0), "r"(b1));
}
__device__ __forceinline__ u32 pkhf(__half a, __half b) {
    __half2 t(a, b);                        // .x at low halfword
    return *(u32*)&t;
}
#define CP_A16(dst, src) \
    asm volatile("cp.async.cg.shared.global [%0], [%1], 16;" \
                 :: "r"(dst), "l"(src) : "memory")
#define CP_COMMIT()  asm volatile("cp.async.commit_group;" ::: "memory")
#define CP_WAIT(N)   asm volatile("cp.async.wait_group %0;" :: "n"(N) : "memory")

// ---------------------------------------------------------------------------
// W fp32 -> fp16 conversion. grid (512, 2), block 256. 131072 float4 per t.
// ---------------------------------------------------------------------------
__global__ __launch_bounds__(256)
void wconv_kernel(const float* __restrict__ wk, const float* __restrict__ wv)
{
    const float* src = blockIdx.y ? wv : wk;
    __half* dst = g_w16 + (size_t)blockIdx.y * 524288;
    int i = blockIdx.x * 256 + threadIdx.x;
    float4 v = ((const float4*)src)[i];
    uint2 o;
    o.x = pkhf(__float2half_rn(v.x), __float2half_rn(v.y));
    o.y = pkhf(__float2half_rn(v.z), __float2half_rn(v.w));
    ((uint2*)dst)[i] = o;
}

// ---------------------------------------------------------------------------
// Compression via HMMA. grid (16 nbg, 4 bh, 2 t), block 256 (8 warps).
// Per CTA: C[16 nb, 128 d] = A[16, 4096]·W[4096, 128], K streamed as 32
// blk-chunks of 128 e-values. A[nb, blk*128+dd] = x[(nb0+nb)*16+blk][dd] +
// pe[blk][dd], staged fp32-add + fp16-convert into a 4KB swizzled buffer.
// W chunks (32KB fp16, k-major [e][d]) stream via cp.async double-buffer
// from g_w16; B fragments via ldmatrix.x4.trans. Warp w owns d-cols w*16.
// cp.async LEDGER: prologue commits w0, w1; every loop iter commits exactly
// ONE group (empty when blk+2 >= 32) after the compute-done sync, then
// CP_WAIT(1) drains w_{blk+1}. Buffer reuse is barrier-protected.
// SMEM: A 2x4KB @0 | W 2x32KB @8192   total 73,728 B   (2 CTAs/SM)
// ---------------------------------------------------------------------------
#define CM_A_OFF 0
#define CM_W_OFF 8192
#define CM_SMEM  73728

__global__ __launch_bounds__(256, 2)
void compress_mma(const float* __restrict__ kin, const float* __restrict__ vin,
                  const float* __restrict__ pek, const float* __restrict__ pev)
{
    extern __shared__ char smc[];
    const u32 sb = smem_u32(smc);

    const int nbg = blockIdx.x;              // 0..15
    const int bh  = blockIdx.y;              // b*2+h
    const int b   = bh >> 1, h = bh & 1;
    const int t   = blockIdx.z;              // 0=k, 1=v

    const float*  x    = t ? vin : kin;
    const float*  pe   = t ? pev : pek;
    const __half* w16g = g_w16 + (size_t)t * 524288;

    const int tid  = threadIdx.x;
    const int w    = tid >> 5;
    const int lane = tid & 31;
    const int li = lane & 15, lh = lane >> 4;
    const int gq = lane >> 2, tq = lane & 3;
    const int dw = w * 16;                   // warp's d-range [dw, dw+16)
    const int nb0 = nbg * 16;

    // -- A stage: chunk blk -> Abuf[buf] (16 rows x 128 e fp16, swizzled) --
    auto a_stage = [&](int blk, int buf) {
        const int row = tid >> 4;            // 0..15
        const int c2  = tid & 15;
        const int nb  = nb0 + row;
        const float* xrowp = x + ((size_t)(b * SEQ + nb * 16 + blk) * HKV + h) * DIM;
        const float* pep   = pe + blk * 128;
        char* abase = smc + CM_A_OFF + buf * 4096;
#pragma unroll
        for (int j = 0; j < 4; ++j) {
            int e2 = c2 + 16 * j;            // u32 index; dd = e2*2
            float2 xv = make_float2(0.f, 0.f);
            if (nb < NBL) xv = *(const float2*)(xrowp + e2 * 2);
            float2 pv = *(const float2*)(pep + e2 * 2);
            u32 off = (u32)row * 256 + ((((u32)e2 >> 2) ^ (row & 7)) << 4) + (e2 & 3) * 4;
            *(u32*)(abase + off) = pkhf(__float2half_rn(xv.x + pv.x),
                                        __float2half_rn(xv.y + pv.y));
        }
    };
    // -- W stage: chunk blk -> Wbuf[buf] via cp.async (128 e x 128 d fp16) --
    auto w_stage = [&](int blk, int buf) {
        const __half* wp = w16g + (size_t)blk * 16384;
        for (int u = tid; u < 2048; u += 256) {
            int e = u >> 4, cc = u & 15;
            u32 dst = sb + CM_W_OFF + buf * 32768
                    + (u32)e * 256 + (u32)((cc ^ (e & 7)) << 4);
            CP_A16(dst, wp + e * 128 + cc * 8);
        }
    };

    float acc[8];
#pragma unroll
    for (int i = 0; i < 8; ++i) acc[i] = 0.f;

    // prologue: w0, w1 committed; A0 staged; drain w0
    w_stage(0, 0); CP_COMMIT();
    w_stage(1, 1); CP_COMMIT();
    a_stage(0, 0);
    CP_WAIT(1);
    __syncthreads();

    for (int blk = 0; blk < 32; ++blk) {
        const int buf = blk & 1;
        // compute chunk blk: 8 k16 steps
#pragma unroll
        for (int ks = 0; ks < 8; ++ks) {
            u32 a4[4];
            ldsm4(a4, sb + CM_A_OFF + buf * 4096
                      + (u32)li * 256 + ((((u32)(ks * 2 + lh)) ^ (li & 7)) << 4));
            u32 b4[4];
            int e = ks * 16 + ((lane >> 3) & 1) * 8 + (lane & 7);
            u32 cd = (u32)((dw >> 3) + (lane >> 4));
            ldsm4t(b4, sb + CM_W_OFF + buf * 32768
                       + (u32)e * 256 + ((cd ^ (e & 7)) << 4));
            mma16816(acc,     a4, b4[0], b4[1]);   // n-tile dw..dw+8
            mma16816(acc + 4, a4, b4[2], b4[3]);   // n-tile dw+8..dw+16
        }
        __syncthreads();                      // all reads of buf done
        if (blk + 2 < 32) w_stage(blk + 2, buf);
        CP_COMMIT();                          // ALWAYS one group per iter
        if (blk + 1 < 32) a_stage(blk + 1, (blk + 1) & 1);
        CP_WAIT(1);                           // drains w_{blk+1}
        __syncthreads();
    }

    // -- Epilogue: C frags -> global fp16 outputs --
    const int nbr0 = nb0 + gq, nbr1 = nb0 + gq + 8;
    if (t == 0) {
        __half* base = g_k16 + (size_t)(bh * 256) * 128;
        if (nbr0 < NBL) {
            __half* p = base + (size_t)nbr0 * 128 + dw + 2 * tq;
            *(u32*)p       = pkhf(__float2half_rn(acc[0]), __float2half_rn(acc[1]));
            *(u32*)(p + 8) = pkhf(__float2half_rn(acc[4]), __float2half_rn(acc[5]));
        }
        if (nbr1 < NBL) {
            __half* p = base + (size_t)nbr1 * 128 + dw + 2 * tq;
            *(u32*)p       = pkhf(__float2half_rn(acc[2]), __float2half_rn(acc[3]));
            *(u32*)(p + 8) = pkhf(__float2half_rn(acc[6]), __float2half_rn(acc[7]));
        }
    } else {
        __half* vb = g_vt16 + (size_t)(bh * 128) * 256;
        const int d0 = dw + 2 * tq;
        if (nbr0 < NBL) {
            vb[(size_t)d0 * 256 + nbr0]       = __float2half_rn(acc[0]);
            vb[(size_t)(d0 + 1) * 256 + nbr0] = __float2half_rn(acc[1]);
            vb[(size_t)(d0 + 8) * 256 + nbr0] = __float2half_rn(acc[4]);
            vb[(size_t)(d0 + 9) * 256 + nbr0] = __float2half_rn(acc[5]);
        }
        if (nbr1 < NBL) {
            vb[(size_t)d0 * 256 + nbr1]       = __float2half_rn(acc[2]);
            vb[(size_t)(d0 + 1) * 256 + nbr1] = __float2half_rn(acc[3]);
            vb[(size_t)(d0 + 8) * 256 + nbr1] = __float2half_rn(acc[6]);
            vb[(size_t)(d0 + 9) * 256 + nbr1] = __float2half_rn(acc[7]);
        }
    }
}

// ---------------------------------------------------------------------------
// Attention kernel — fp16 warp MMA, 3 CTAs/SM. VERBATIM from R12 (passing).
// ---------------------------------------------------------------------------
#define SM_RMAX  0
#define SM_RSUM  1024
#define SM_Q     2048
#define SM_K     18432
#define SM_P     SM_K
#define SM_V0    51200
#define SM_V1    61440
#define ATT_SMEM 71680

__global__ __launch_bounds__(256, 3)
void attn_kernel(const float* __restrict__ q, float* __restrict__ out,
                 float* __restrict__ attn, int write_attn)
{
    extern __shared__ char smc[];
    const u32 sb = smem_u32(smc);
    float* rmax = (float*)(smc + SM_RMAX);   // [4 c4][64 rows]
    float* rsum = (float*)(smc + SM_RSUM);

    const int st = 63 - blockIdx.x;          // heavy-first
    const int g  = blockIdx.y;
    const int bh = blockIdx.z;
    const int b  = bh >> 1, h = bh & 1;
    const int hq = h * GRP + g;
    const int s0 = st * 64;
    const int tid  = threadIdx.x;
    const int w    = tid >> 5;
    const int lane = tid & 31;
    const int r2 = w >> 2, c4 = w & 3;
    const int gq = lane >> 2, tq = lane & 3;
    const int li = lane & 15, lh = lane >> 4;

    const int NVC = st * 4 + 3;              // max valid col count (odd)
    const int KR  = (NVC + 15) & ~15;        // total valid K rows (<=256)
    const int KR0 = min(KR, 128);
    const int KR1 = KR - KR0;                // >0 iff st>=32
    const int rbase = r2 * 32;
    const size_t bhoff = (size_t)bh * 32768;

    const int KSC = KR >> 4;                 // k16 steps for phase C (<=16)
    const int nch = (KSC + 1) >> 1;          // 32-nb V chunks (<=8)

    // ---- group 1: K half0 ----
    for (int u = tid; u < KR0 * 16; u += 256) {
        int nb = u >> 4, c = u & 15;
        u32 dst = sb + SM_K + (u32)nb * 256 + (u32)((c ^ (nb & 7)) << 4);
        CP_A16(dst, g_k16 + bhoff + nb * 128 + c * 8);
    }
    CP_COMMIT();
    // ---- group 2: V chunk 0 ----
    for (int u = tid; u < 512; u += 256) {
        int dd = u >> 2, cc = u & 3;
        CP_A16(sb + SM_V0 + (u32)dd * 80 + (u32)cc * 16,
               g_vt16 + bhoff + dd * 256 + cc * 8);
    }
    CP_COMMIT();
    // ---- group 3: V chunk 1 (EMPTY group when nch==1 — keeps the count) ----
    if (nch > 1) {
        for (int u = tid; u < 512; u += 256) {
            int dd = u >> 2, cc = u & 3;
            CP_A16(sb + SM_V1 + (u32)dd * 80 + (u32)cc * 16,
                   g_vt16 + bhoff + dd * 256 + 32 + cc * 8);
        }
    }
    CP_COMMIT();                              // ALWAYS the 3rd group
    // ---- Stage Q (f32 -> fp16), swizzled 256B rows ----
    for (int u = tid; u < 4096; u += 256) {
        int r = u >> 6, k2 = u & 63;
        float2 qv = *(const float2*)(q + ((size_t)((b * SEQ + s0 + r) * HQN + hq)) * DIM + k2 * 2);
        u32 off = (u32)r * 256 + (((((u32)k2) >> 2) ^ (r & 7)) << 4) + (k2 & 3) * 4;
        *(u32*)(smc + SM_Q + off) = pkhf(__float2half_rn(qv.x), __float2half_rn(qv.y));
    }
    CP_WAIT(2);                               // drains K half0 (3 groups committed)
    __syncthreads();

    // ---- Phase A: D[2 half][8 tile][4]; warp covers 32 cols per half ----
    float D[16][4];
#pragma unroll
    for (int i = 0; i < 16; ++i) { D[i][0] = D[i][1] = D[i][2] = D[i][3] = 0.f; }

#pragma unroll
    for (int hk = 0; hk < 2; ++hk) {
        if (hk == 1) {
            if (KR1 <= 0) break;
            __syncthreads();                  // all reads of K half0 done
            for (int u = tid; u < KR1 * 16; u += 256) {
                int nb = u >> 4, c = u & 15;
                u32 dst = sb + SM_K + (u32)nb * 256 + (u32)((c ^ (nb & 7)) << 4);
                CP_A16(dst, g_k16 + bhoff + (128 + nb) * 128 + c * 8);
            }
            CP_COMMIT();
            CP_WAIT(0);                       // drains V0/V1 too (issued early)
            __syncthreads();
        }
        const int cw = hk * 128 + c4 * 32;    // warp's first score col
        int jt = (NVC - cw + 7) >> 3;
        jt = (jt < 0) ? 0 : ((jt > 4) ? 4 : jt);
        const int ph = (jt + 1) >> 1;         // 16-col pairs (<=2)
        for (int ks = 0; ks < 8; ++ks) {
            u32 a2[2][4];
            const u32 ci = (u32)(ks * 2 + lh);
#pragma unroll
            for (int sp = 0; sp < 2; ++sp) {
                int ri = rbase + sp * 16 + li;
                ldsm4(a2[sp], sb + SM_Q + (u32)ri * 256 + ((ci ^ (ri & 7)) << 4));
            }
            for (int jp = 0; jp < ph; ++jp) {
                int ri = c4 * 32 + jp * 16 + li;      // local K row
                u32 b4[4];
                ldsm4(b4, sb + SM_K + (u32)ri * 256 + ((ci ^ (ri & 7)) << 4));
#pragma unroll
                for (int sp = 0; sp < 2; ++sp) {
                    mma16816(D[hk * 8 + sp * 4 + 2 * jp],     a2[sp], b4[0], b4[2]);
                    mma16816(D[hk * 8 + sp * 4 + 2 * jp + 1], a2[sp], b4[1], b4[3]);
                }
            }
        }
    }

    // ---- Softmax: local max -> B1 ----
#pragma unroll
    for (int slot = 0; slot < 4; ++slot) {
        int sp = slot >> 1, hf = slot & 1;
        int row = rbase + sp * 16 + gq + hf * 8;
        int s = s0 + row;
        int nv = (s >= 31) ? (((s - 31) >> 4) + 1) : 0;
        float mloc = -1e30f;
#pragma unroll
        for (int hk = 0; hk < 2; ++hk)
#pragma unroll
            for (int j = 0; j < 4; ++j) {
                int c0 = hk * 128 + c4 * 32 + j * 8 + 2 * tq;
                float* dd = D[hk * 8 + sp * 4 + j];
                if (c0     < nv) mloc = fmaxf(mloc, dd[hf * 2]     * SCALE);
                if (c0 + 1 < nv) mloc = fmaxf(mloc, dd[hf * 2 + 1] * SCALE);
            }
        mloc = fmaxf(mloc, __shfl_xor_sync(0xffffffffu, mloc, 1));
        mloc = fmaxf(mloc, __shfl_xor_sync(0xffffffffu, mloc, 2));
        if (tq == 0) rmax[c4 * 64 + row] = mloc;
    }
    __syncthreads();                          // B1

    // ---- Softmax: exp + sum -> B2 ----
#pragma unroll
    for (int slot = 0; slot < 4; ++slot) {
        int sp = slot >> 1, hf = slot & 1;
        int row = rbase + sp * 16 + gq + hf * 8;
        int s = s0 + row;
        int nv = (s >= 31) ? (((s - 31) >> 4) + 1) : 0;
        float m = fmaxf(fmaxf(rmax[row], rmax[64 + row]),
                        fmaxf(rmax[128 + row], rmax[192 + row]));
        float sl = 0.f;
#pragma unroll
        for (int hk = 0; hk < 2; ++hk)
#pragma unroll
            for (int j = 0; j < 4; ++j) {
                int c0 = hk * 128 + c4 * 32 + j * 8 + 2 * tq;
                float* dd = D[hk * 8 + sp * 4 + j];
                float e0 = (c0     < nv) ? __expf(dd[hf * 2]     * SCALE - m) : 0.f;
                float e1 = (c0 + 1 < nv) ? __expf(dd[hf * 2 + 1] * SCALE - m) : 0.f;
                dd[hf * 2]     = e0;
                dd[hf * 2 + 1] = e1;
                sl += e0 + e1;
            }
        sl += __shfl_xor_sync(0xffffffffu, sl, 1);
        sl += __shfl_xor_sync(0xffffffffu, sl, 2);
        if (tq == 0) rsum[c4 * 64 + row] = sl;
    }
    __syncthreads();                          // B2: K reads done -> P may overlay

    // ---- Normalize + attn write (scalar: NBL odd!) + P -> smem fp16 ----
#pragma unroll
    for (int slot = 0; slot < 4; ++slot) {
        int sp = slot >> 1, hf = slot & 1;
        int row = rbase + sp * 16 + gq + hf * 8;
        float tot = rsum[row] + rsum[64 + row] + rsum[128 + row] + rsum[192 + row];
        float inv = 1.f / fmaxf(tot, 1e-20f);
        size_t arow = (((size_t)b * HQN + hq) * SEQ + s0 + row) * NBL;
#pragma unroll
        for (int hk = 0; hk < 2; ++hk)
#pragma unroll
            for (int j = 0; j < 4; ++j) {
                int c0 = hk * 128 + c4 * 32 + j * 8 + 2 * tq;
                float* dd = D[hk * 8 + sp * 4 + j];
                float p0 = dd[hf * 2]     * inv;
                float p1 = dd[hf * 2 + 1] * inv;
                if (write_attn) {
                    attn[arow + c0] = p0;             // c0 <= 254 always
                    if (c0 + 1 < NBL) attn[arow + c0 + 1] = p1;
                }
                u32 ch = (u32)((hk * 16 + c4 * 4 + j) ^ (row & 7));
                u32 off = (u32)row * 512 + (ch << 4) + tq * 4;
                *(u32*)(smc + SM_P + off) = pkhf(__float2half_rn(p0), __float2half_rn(p1));
            }
    }
    __syncthreads();                          // B3: P visible

    // ---- Phase C: 32-nb V chunks, double-buffered ----
    const int dbase = c4 * 32;
    float C[8][4];
#pragma unroll
    for (int i = 0; i < 8; ++i) { C[i][0] = C[i][1] = C[i][2] = C[i][3] = 0.f; }

    for (int kc = 0; kc < nch; ++kc) {
        if (kc + 1 < nch) { CP_WAIT(1); }     // pending ⊆ {V_kc, V_kc+1} -> drains V_kc
        else             { CP_WAIT(0); }      // LAST chunk: nothing younger -> full drain
        __syncthreads();
        const u32 sbV = sb + ((kc & 1) ? SM_V1 : SM_V0);
        const int kslo = kc * 2;
        const int kshi = min(kslo + 2, KSC);
        for (int ks = kslo; ks < kshi; ++ks) {
            u32 p2[2][4];
            const u32 ciP = (u32)(ks * 2 + lh);
#pragma unroll
            for (int sp = 0; sp < 2; ++sp) {
                int ri = rbase + sp * 16 + li;
                ldsm4(p2[sp], sb + SM_P + (u32)ri * 512 + ((ciP ^ (ri & 7)) << 4));
            }
            const u32 ciV = (u32)((ks - kslo) * 2 + lh);
#pragma unroll
            for (int dp = 0; dp < 2; ++dp) {
                int ri = dbase + dp * 16 + li;
                u32 b4[4];
                ldsm4(b4, sbV + (u32)ri * 80 + ciV * 16);
#pragma unroll
                for (int sp = 0; sp < 2; ++sp) {
                    mma16816(C[sp * 4 + 2 * dp],     p2[sp], b4[0], b4[2]);
                    mma16816(C[sp * 4 + 2 * dp + 1], p2[sp], b4[1], b4[3]);
                }
            }
        }
        __syncthreads();                      // reads of chunk kc done
        if (kc + 2 < nch) {
            const u32 dstb = sb + ((kc & 1) ? SM_V1 : SM_V0);
            for (int u = tid; u < 512; u += 256) {
                int dd = u >> 2, cc = u & 3;
                CP_A16(dstb + (u32)dd * 80 + (u32)cc * 16,
                       g_vt16 + bhoff + dd * 256 + (kc + 2) * 32 + cc * 8);
            }
            CP_COMMIT();
        }
    }

    // ---- Store out: (BS, S, HQ, D), float2 per fragment pair ----
#pragma unroll
    for (int slot = 0; slot < 4; ++slot) {
        int sp = slot >> 1, hf = slot & 1;
        int row = rbase + sp * 16 + gq + hf * 8;
        float* op = out + ((size_t)(b * SEQ + s0 + row) * HQN + hq) * DIM + dbase;
#pragma unroll
        for (int dt = 0; dt < 4; ++dt) {
            *(float2*)(op + dt * 8 + 2 * tq) =
                make_float2(C[sp * 4 + dt][hf * 2], C[sp * 4 + dt][hf * 2 + 1]);
        }
    }
}

// ---------------------------------------------------------------------------
extern "C" void kernel_launch(void* const* d_in, const int* in_sizes, int n_in,
                              void* d_out, int out_size)
{
    const float* q   = (const float*)d_in[0];
    const float* k   = (const float*)d_in[1];
    const float* v   = (const float*)d_in[2];
    // d_in[3] = cu_seqlens_k (fixed [0,S,2S]) — unused
    const float* wk  = (const float*)d_in[4];
    const float* wv  = (const float*)d_in[5];
    const float* pek = (const float*)d_in[6];
    const float* pev = (const float*)d_in[7];

    float* out  = (float*)d_out;
    float* attn = out + OUT_ELEMS;
    int write_attn = ((size_t)out_size >= OUT_ELEMS + ATTN_ELEMS) ? 1 : 0;

    cudaFuncSetAttribute(compress_mma,
                         cudaFuncAttributeMaxDynamicSharedMemorySize, CM_SMEM);
    cudaFuncSetAttribute(attn_kernel,
                         cudaFuncAttributeMaxDynamicSharedMemorySize, ATT_SMEM);

    wconv_kernel<<<dim3(512, 2), 256>>>(wk, wv);
    compress_mma<<<dim3(16, 4, 2), 256, CM_SMEM>>>(k, v, pek, pev);
    attn_kernel<<<dim3(64, 16, 4), 256, ATT_SMEM>>>(q, out, attn, write_attn);
}